// round 11
// baseline (speedup 1.0000x reference)
#include <cuda_runtime.h>
#include <cuda_fp16.h>
#include <cstdint>

#define BB  2
#define SS  2048
#define DMM 1024
#define HH  16
#define DHH 64
#define BH  (BB*HH)   // 32

// ---------------- scratch (device globals; no runtime allocation) ----------------
__device__ float g_q[BB*HH*SS*DHH];
__device__ float g_k[BB*HH*SS*DHH];
__device__ float g_v[BB*HH*SS*DHH];
__device__ float g_att[BB*SS*DMM];
__device__ float g_erT[DHH*SS];          // Er[0:2048] transposed: [64][2048]
__device__ __half g_rel[134217728];      // PRE-SKEWED fp16: [BH][q][k] = Q[q]·Er[k+2047-q]

// ---------------- helpers ----------------
__device__ __forceinline__ uint32_t f2tf(float f) {
    uint32_t u;
    asm("cvt.rna.tf32.f32 %0, %1;" : "=r"(u) : "f"(f));
    return u;
}

__device__ __forceinline__ void mma_tf32(float* c, const uint32_t* a, const uint32_t* b) {
    asm("mma.sync.aligned.m16n8k8.row.col.f32.tf32.tf32.f32 "
        "{%0,%1,%2,%3},{%4,%5,%6,%7},{%8,%9},{%0,%1,%2,%3};"
        : "+f"(c[0]), "+f"(c[1]), "+f"(c[2]), "+f"(c[3])
        : "r"(a[0]), "r"(a[1]), "r"(a[2]), "r"(a[3]), "r"(b[0]), "r"(b[1]));
}

// ---------------- Er transpose ----------------
__global__ void k_transpose_er(const float* __restrict__ Er) {
    int idx = blockIdx.x * 256 + threadIdx.x;   // 0 .. 64*2048-1
    int r = idx & 2047;
    int d = idx >> 11;
    g_erT[idx] = Er[r * 64 + d];
}

// ---------------- fused QKV projection, TF32 tensor-core GEMM ----------------
#define AS_STRIDE 20
#define BS_STRIDE 136
__global__ __launch_bounds__(256, 2) void k_qkv(
    const float* __restrict__ x,
    const float* __restrict__ Wq, const float* __restrict__ Wk, const float* __restrict__ Wv,
    const float* __restrict__ bq, const float* __restrict__ bk, const float* __restrict__ bv)
{
    __shared__ uint32_t As[2][128 * AS_STRIDE];
    __shared__ uint32_t Bs[2][16 * BS_STRIDE];

    int bx = blockIdx.x, by = blockIdx.y;
    int which = bx >> 3;
    const float* W    = (which == 0) ? Wq : ((which == 1) ? Wk : Wv);
    const float* bias = (which == 0) ? bq : ((which == 1) ? bk : bv);
    float*       dst  = (which == 0) ? g_q : ((which == 1) ? g_k : g_v);
    int nb = (bx & 7) * 128;
    int bm = by * 128;

    int tid = threadIdx.x;
    int lane = tid & 31, wid = tid >> 5;
    int warpM = wid >> 2, warpN = wid & 3;
    int g = lane >> 2, tg = lane & 3;
    int arow = tid >> 2, ac = (tid & 3) * 4;
    int brow = tid >> 5, bc = (tid & 31) * 4;

    const float* Ap = x + (size_t)(bm + arow) * DMM + ac;
    const float* Bp = W + (size_t)brow * DMM + nb + bc;

    {
        float4 a0 = *(const float4*)Ap;
        float4 a1 = *(const float4*)(Ap + (size_t)64 * DMM);
        float4 b0 = *(const float4*)Bp;
        float4 b1 = *(const float4*)(Bp + (size_t)8 * DMM);
        uint32_t* p;
        p = &As[0][arow * AS_STRIDE + ac];
        p[0] = f2tf(a0.x); p[1] = f2tf(a0.y); p[2] = f2tf(a0.z); p[3] = f2tf(a0.w);
        p = &As[0][(arow + 64) * AS_STRIDE + ac];
        p[0] = f2tf(a1.x); p[1] = f2tf(a1.y); p[2] = f2tf(a1.z); p[3] = f2tf(a1.w);
        p = &Bs[0][brow * BS_STRIDE + bc];
        p[0] = f2tf(b0.x); p[1] = f2tf(b0.y); p[2] = f2tf(b0.z); p[3] = f2tf(b0.w);
        p = &Bs[0][(brow + 8) * BS_STRIDE + bc];
        p[0] = f2tf(b1.x); p[1] = f2tf(b1.y); p[2] = f2tf(b1.z); p[3] = f2tf(b1.w);
    }
    __syncthreads();

    float c[4][4][4];
#pragma unroll
    for (int mt = 0; mt < 4; mt++)
#pragma unroll
        for (int nt = 0; nt < 4; nt++)
#pragma unroll
            for (int r = 0; r < 4; r++) c[mt][nt][r] = 0.f;

    for (int it = 0; it < 64; it++) {
        int cur = it & 1;
        float4 a0, a1, b0, b1;
        bool more = (it < 63);
        if (more) {
            const float* Ap2 = Ap + (it + 1) * 16;
            const float* Bp2 = Bp + (size_t)(it + 1) * 16 * DMM;
            a0 = *(const float4*)Ap2;
            a1 = *(const float4*)(Ap2 + (size_t)64 * DMM);
            b0 = *(const float4*)Bp2;
            b1 = *(const float4*)(Bp2 + (size_t)8 * DMM);
        }
#pragma unroll
        for (int ks2 = 0; ks2 < 2; ks2++) {
            int ks = ks2 * 8;
            uint32_t af[4][4], bf[4][2];
#pragma unroll
            for (int mt = 0; mt < 4; mt++) {
                int rb = warpM * 64 + mt * 16;
                af[mt][0] = As[cur][(rb + g)     * AS_STRIDE + ks + tg];
                af[mt][1] = As[cur][(rb + g + 8) * AS_STRIDE + ks + tg];
                af[mt][2] = As[cur][(rb + g)     * AS_STRIDE + ks + tg + 4];
                af[mt][3] = As[cur][(rb + g + 8) * AS_STRIDE + ks + tg + 4];
            }
#pragma unroll
            for (int nt = 0; nt < 4; nt++) {
                int cb = warpN * 32 + nt * 8;
                bf[nt][0] = Bs[cur][(ks + tg)     * BS_STRIDE + cb + g];
                bf[nt][1] = Bs[cur][(ks + tg + 4) * BS_STRIDE + cb + g];
            }
#pragma unroll
            for (int mt = 0; mt < 4; mt++)
#pragma unroll
                for (int nt = 0; nt < 4; nt++)
                    mma_tf32(c[mt][nt], af[mt], bf[nt]);
        }
        if (more) {
            int nxt = cur ^ 1;
            uint32_t* p;
            p = &As[nxt][arow * AS_STRIDE + ac];
            p[0] = f2tf(a0.x); p[1] = f2tf(a0.y); p[2] = f2tf(a0.z); p[3] = f2tf(a0.w);
            p = &As[nxt][(arow + 64) * AS_STRIDE + ac];
            p[0] = f2tf(a1.x); p[1] = f2tf(a1.y); p[2] = f2tf(a1.z); p[3] = f2tf(a1.w);
            p = &Bs[nxt][brow * BS_STRIDE + bc];
            p[0] = f2tf(b0.x); p[1] = f2tf(b0.y); p[2] = f2tf(b0.z); p[3] = f2tf(b0.w);
            p = &Bs[nxt][(brow + 8) * BS_STRIDE + bc];
            p[0] = f2tf(b1.x); p[1] = f2tf(b1.y); p[2] = f2tf(b1.z); p[3] = f2tf(b1.w);
            __syncthreads();
        }
    }

#pragma unroll
    for (int mt = 0; mt < 4; mt++) {
#pragma unroll
        for (int nt = 0; nt < 4; nt++) {
            int nloc = nb + warpN * 32 + nt * 8 + 2 * tg;
            int h = nloc >> 6, d = nloc & 63;
            float b0v = bias[nloc], b1v = bias[nloc + 1];
            int m0 = bm + warpM * 64 + mt * 16 + g;
            int m1 = m0 + 8;
            {
                int b = m0 >> 11, s = m0 & 2047;
                float2 o; o.x = c[mt][nt][0] + b0v; o.y = c[mt][nt][1] + b1v;
                *(float2*)&dst[(((size_t)b * HH + h) * SS + s) * DHH + d] = o;
            }
            {
                int b = m1 >> 11, s = m1 & 2047;
                float2 o; o.x = c[mt][nt][2] + b0v; o.y = c[mt][nt][3] + b1v;
                *(float2*)&dst[(((size_t)b * HH + h) * SS + s) * DHH + d] = o;
            }
        }
    }
}

// ---------------- REL GEMM (TF32), skewed fp16 store: g_rel[q][k] = Q[q]·Er[k+2047-q] ----------------
__global__ __launch_bounds__(256, 2) void k_rel()
{
    int bh = blockIdx.z;
    int r0 = blockIdx.x * 128, q0 = blockIdx.y * 128;
    if (q0 + r0 < 1793) return;

    __shared__ uint32_t As[2][128 * AS_STRIDE];
    __shared__ uint32_t Bs[2][16 * BS_STRIDE];

    const float* A = g_q + (size_t)bh * SS * DHH;

    int tid = threadIdx.x;
    int lane = tid & 31, wid = tid >> 5;
    int warpM = wid >> 2, warpN = wid & 3;
    int g = lane >> 2, tg = lane & 3;
    int arow = tid >> 2, ac = (tid & 3) * 4;
    int brow = tid >> 5, bc = (tid & 31) * 4;

    const float* Ap = A + (size_t)(q0 + arow) * DHH + ac;
    const float* Bp = g_erT + (size_t)brow * SS + r0 + bc;

    {
        float4 a0 = *(const float4*)Ap;
        float4 a1 = *(const float4*)(Ap + (size_t)64 * DHH);
        float4 b0 = *(const float4*)Bp;
        float4 b1 = *(const float4*)(Bp + (size_t)8 * SS);
        uint32_t* p;
        p = &As[0][arow * AS_STRIDE + ac];
        p[0] = f2tf(a0.x); p[1] = f2tf(a0.y); p[2] = f2tf(a0.z); p[3] = f2tf(a0.w);
        p = &As[0][(arow + 64) * AS_STRIDE + ac];
        p[0] = f2tf(a1.x); p[1] = f2tf(a1.y); p[2] = f2tf(a1.z); p[3] = f2tf(a1.w);
        p = &Bs[0][brow * BS_STRIDE + bc];
        p[0] = f2tf(b0.x); p[1] = f2tf(b0.y); p[2] = f2tf(b0.z); p[3] = f2tf(b0.w);
        p = &Bs[0][(brow + 8) * BS_STRIDE + bc];
        p[0] = f2tf(b1.x); p[1] = f2tf(b1.y); p[2] = f2tf(b1.z); p[3] = f2tf(b1.w);
    }
    __syncthreads();

    float c[4][4][4];
#pragma unroll
    for (int mt = 0; mt < 4; mt++)
#pragma unroll
        for (int nt = 0; nt < 4; nt++)
#pragma unroll
            for (int r = 0; r < 4; r++) c[mt][nt][r] = 0.f;

    for (int it = 0; it < 4; it++) {
        int cur = it & 1;
        float4 a0, a1, b0, b1;
        bool more = (it < 3);
        if (more) {
            const float* Ap2 = Ap + (it + 1) * 16;
            const float* Bp2 = Bp + (size_t)(it + 1) * 16 * SS;
            a0 = *(const float4*)Ap2;
            a1 = *(const float4*)(Ap2 + (size_t)64 * DHH);
            b0 = *(const float4*)Bp2;
            b1 = *(const float4*)(Bp2 + (size_t)8 * SS);
        }
#pragma unroll
        for (int ks2 = 0; ks2 < 2; ks2++) {
            int ks = ks2 * 8;
            uint32_t af[4][4], bf[4][2];
#pragma unroll
            for (int mt = 0; mt < 4; mt++) {
                int rb = warpM * 64 + mt * 16;
                af[mt][0] = As[cur][(rb + g)     * AS_STRIDE + ks + tg];
                af[mt][1] = As[cur][(rb + g + 8) * AS_STRIDE + ks + tg];
                af[mt][2] = As[cur][(rb + g)     * AS_STRIDE + ks + tg + 4];
                af[mt][3] = As[cur][(rb + g + 8) * AS_STRIDE + ks + tg + 4];
            }
#pragma unroll
            for (int nt = 0; nt < 4; nt++) {
                int cb = warpN * 32 + nt * 8;
                bf[nt][0] = Bs[cur][(ks + tg)     * BS_STRIDE + cb + g];
                bf[nt][1] = Bs[cur][(ks + tg + 4) * BS_STRIDE + cb + g];
            }
#pragma unroll
            for (int mt = 0; mt < 4; mt++)
#pragma unroll
                for (int nt = 0; nt < 4; nt++)
                    mma_tf32(c[mt][nt], af[mt], bf[nt]);
        }
        if (more) {
            int nxt = cur ^ 1;
            uint32_t* p;
            p = &As[nxt][arow * AS_STRIDE + ac];
            p[0] = f2tf(a0.x); p[1] = f2tf(a0.y); p[2] = f2tf(a0.z); p[3] = f2tf(a0.w);
            p = &As[nxt][(arow + 64) * AS_STRIDE + ac];
            p[0] = f2tf(a1.x); p[1] = f2tf(a1.y); p[2] = f2tf(a1.z); p[3] = f2tf(a1.w);
            p = &Bs[nxt][brow * BS_STRIDE + bc];
            p[0] = f2tf(b0.x); p[1] = f2tf(b0.y); p[2] = f2tf(b0.z); p[3] = f2tf(b0.w);
            p = &Bs[nxt][(brow + 8) * BS_STRIDE + bc];
            p[0] = f2tf(b1.x); p[1] = f2tf(b1.y); p[2] = f2tf(b1.z); p[3] = f2tf(b1.w);
            __syncthreads();
        }
    }

    // skewed epilogue: element (m, col) -> g_rel[m][col - (2047 - m)] when in causal band
    __half* C = g_rel + (size_t)bh * SS * SS;
#pragma unroll
    for (int mt = 0; mt < 4; mt++) {
#pragma unroll
        for (int nt = 0; nt < 4; nt++) {
            int col = r0 + warpN * 32 + nt * 8 + 2 * tg;
            int m0 = q0 + warpM * 64 + mt * 16 + g;
            int m1 = m0 + 8;
            int k0e = col - 2047 + m0;
            int k1e = col - 2047 + m1;
            if (k0e >= 0)     C[(size_t)m0 * SS + k0e]     = __float2half(c[mt][nt][0]);
            if (k0e + 1 >= 0) C[(size_t)m0 * SS + k0e + 1] = __float2half(c[mt][nt][1]);
            if (k1e >= 0)     C[(size_t)m1 * SS + k1e]     = __float2half(c[mt][nt][2]);
            if (k1e + 1 >= 0) C[(size_t)m1 * SS + k1e + 1] = __float2half(c[mt][nt][3]);
        }
    }
}

// ---------------- flash attention, TF32 tensor cores, 256 threads, 2 CTAs/SM ----------------
// 8 warps x 16 q-rows = 128 q per block. Stage 128 keys per barrier, compute in two
// 64-key sub-tiles (registers stay 2-CTA-safe). K stored with intra-8-group d-pair
// permutation (d -> (d&3)*2 + (d>>2)) so score B-fragment pairs are one LDS.64.
// smem (u32): Ks[128*68] | Vs[128*72] | Ps[128*68] = 26624 u32 = 106496 B (2 CTAs/SM)
#define ATTN_SMEM_U32 (128*68 + 128*72 + 128*68)

__global__ __launch_bounds__(256, 2) void k_attn()
{
    extern __shared__ uint32_t smu[];
    uint32_t* Ks = smu;                  // [key][dperm] stride 68 (raw fp32 bits, d-pair permuted)
    uint32_t* Vs = Ks + 128 * 68;        // [key][d]     stride 72 (raw fp32 bits)
    uint32_t* Ps = Vs + 128 * 72;        // [q][k]       stride 68 (per-warp-private rows)

    int bh = blockIdx.y;
    int qt = (int)gridDim.x - 1 - (int)blockIdx.x;   // heavy tiles first
    int q0 = qt * 128;
    const float*  Q  = g_q + (size_t)bh * SS * DHH;
    const float*  Kp = g_k + (size_t)bh * SS * DHH;
    const float*  Vp = g_v + (size_t)bh * SS * DHH;
    const __half* R  = g_rel + (size_t)bh * SS * SS;

    int tid = threadIdx.x;
    int lane = tid & 31, wid = tid >> 5;   // wid 0..7
    int g = lane >> 2, tg = lane & 3;
    int qbase = q0 + wid * 16;
    int qlo = qbase + g, qhi = qlo + 8;

    // Q A-fragments in registers, loaded once, reused for every k-tile
    uint32_t qa[8][4];
#pragma unroll
    for (int ks = 0; ks < 8; ks++) {
        qa[ks][0] = f2tf(Q[(size_t)qlo * DHH + ks * 8 + tg]);
        qa[ks][1] = f2tf(Q[(size_t)qhi * DHH + ks * 8 + tg]);
        qa[ks][2] = f2tf(Q[(size_t)qlo * DHH + ks * 8 + tg + 4]);
        qa[ks][3] = f2tf(Q[(size_t)qhi * DHH + ks * 8 + tg + 4]);
    }

    float o[8][4];
#pragma unroll
    for (int nt = 0; nt < 8; nt++) { o[nt][0] = o[nt][1] = o[nt][2] = o[nt][3] = 0.f; }
    float mlo = -3.0e38f, mhi = -3.0e38f, llo = 0.f, lhi = 0.f;

    int prow_lo = (wid * 16 + g) * 68;
    int prow_hi = (wid * 16 + g + 8) * 68;

    int nstages = qt + 1;   // 128 keys per stage, keys up to q0+127
    for (int t = 0; t < nstages; t++) {
        __syncthreads();   // prior stage's reads of Ks/Vs done
        // stage 128 keys: K with d-pair permutation, V plain
#pragma unroll
        for (int i = 0; i < 8; i++) {
            int idx = i * 256 + tid;               // 0..2047
            int ki = idx >> 4, c4 = (idx & 15) * 4;
            const float* src = Kp + (size_t)(t * 128 + ki) * DHH + c4;
            uint4 kv = *(const uint4*)src;
            int base = c4 & ~7, off = (c4 >> 2) & 1;
            uint32_t* kp = &Ks[ki * 68 + base + off];
            kp[0] = kv.x; kp[2] = kv.y; kp[4] = kv.z; kp[6] = kv.w;
            uint4 vv = *(const uint4*)(Vp + (size_t)(t * 128 + ki) * DHH + c4);
            *(uint4*)&Vs[ki * 72 + c4] = vv;
        }
        __syncthreads();

#pragma unroll
        for (int sub = 0; sub < 2; sub++) {
            int k0 = t * 128 + sub * 64;
            int kb = sub * 64;   // smem key offset of this sub-tile
            // warp-uniform causal bound (can be <= 0 for low warps at late tiles)
            int ntmax = min(8, ((qbase + 15 - k0) >> 3) + 1);
            if (ntmax > 0) {
                // ---- scores S = Q·K^T (paired B-fragments: one LDS.64 each) ----
                float s[8][4];
#pragma unroll
                for (int nt = 0; nt < 8; nt++) { s[nt][0] = s[nt][1] = s[nt][2] = s[nt][3] = 0.f; }
#pragma unroll
                for (int ks = 0; ks < 8; ks++) {
#pragma unroll
                    for (int nt = 0; nt < 8; nt++) {
                        if (nt < ntmax) {
                            uint2 bp = *(const uint2*)&Ks[(kb + nt * 8 + g) * 68 + ks * 8 + 2 * tg];
                            uint32_t bf[2];
                            bf[0] = bp.x; bf[1] = bp.y;
                            mma_tf32(s[nt], qa[ks], bf);
                        }
                    }
                }

                // ---- + rel bias (fp16, aligned half2), scale, causal mask ----
                float tmlo = -3.0e38f, tmhi = -3.0e38f;
#pragma unroll
                for (int nt = 0; nt < 8; nt++) {
                    if (nt < ntmax) {
                        int kk = k0 + nt * 8 + 2 * tg;
                        float2 rlo = __half22float2(*(const __half2*)&R[(size_t)qlo * SS + kk]);
                        float2 rhi = __half22float2(*(const __half2*)&R[(size_t)qhi * SS + kk]);
                        s[nt][0] = (kk     <= qlo) ? (s[nt][0] + rlo.x) * 0.125f : -1.0e30f;
                        s[nt][1] = (kk + 1 <= qlo) ? (s[nt][1] + rlo.y) * 0.125f : -1.0e30f;
                        s[nt][2] = (kk     <= qhi) ? (s[nt][2] + rhi.x) * 0.125f : -1.0e30f;
                        s[nt][3] = (kk + 1 <= qhi) ? (s[nt][3] + rhi.y) * 0.125f : -1.0e30f;
                        tmlo = fmaxf(tmlo, fmaxf(s[nt][0], s[nt][1]));
                        tmhi = fmaxf(tmhi, fmaxf(s[nt][2], s[nt][3]));
                    }
                }

                // ---- online softmax (rows live in 4 tg lanes -> 2 shfls) ----
                tmlo = fmaxf(tmlo, __shfl_xor_sync(0xffffffffu, tmlo, 1));
                tmlo = fmaxf(tmlo, __shfl_xor_sync(0xffffffffu, tmlo, 2));
                tmhi = fmaxf(tmhi, __shfl_xor_sync(0xffffffffu, tmhi, 1));
                tmhi = fmaxf(tmhi, __shfl_xor_sync(0xffffffffu, tmhi, 2));
                float mnlo = fmaxf(mlo, tmlo), mnhi = fmaxf(mhi, tmhi);
                float clo = __expf(mlo - mnlo), chi = __expf(mhi - mnhi);
                mlo = mnlo; mhi = mnhi;

                float rslo = 0.f, rshi = 0.f;
#pragma unroll
                for (int nt = 0; nt < 8; nt++) {
                    if (nt < ntmax) {
                        float p0 = __expf(s[nt][0] - mnlo);
                        float p1 = __expf(s[nt][1] - mnlo);
                        float p2 = __expf(s[nt][2] - mnhi);
                        float p3 = __expf(s[nt][3] - mnhi);
                        rslo += p0 + p1;
                        rshi += p2 + p3;
                        int col = nt * 8 + 2 * tg;
                        *(uint2*)&Ps[prow_lo + col] = make_uint2(f2tf(p0), f2tf(p1));
                        *(uint2*)&Ps[prow_hi + col] = make_uint2(f2tf(p2), f2tf(p3));
                    }
                }
                rslo += __shfl_xor_sync(0xffffffffu, rslo, 1);
                rslo += __shfl_xor_sync(0xffffffffu, rslo, 2);
                rshi += __shfl_xor_sync(0xffffffffu, rshi, 1);
                rshi += __shfl_xor_sync(0xffffffffu, rshi, 2);
                llo = llo * clo + rslo;
                lhi = lhi * chi + rshi;
#pragma unroll
                for (int nt2 = 0; nt2 < 8; nt2++) {
                    o[nt2][0] *= clo; o[nt2][1] *= clo;
                    o[nt2][2] *= chi; o[nt2][3] *= chi;
                }

                __syncwarp();   // Ps rows are warp-private: warp-level ordering suffices

                // ---- O += P·V (skip k-groups where P == 0) ----
#pragma unroll
                for (int ks = 0; ks < 8; ks++) {
                    if (ks < ntmax) {
                        uint32_t pa[4];
                        pa[0] = Ps[prow_lo + ks * 8 + tg];
                        pa[1] = Ps[prow_hi + ks * 8 + tg];
                        pa[2] = Ps[prow_lo + ks * 8 + tg + 4];
                        pa[3] = Ps[prow_hi + ks * 8 + tg + 4];
#pragma unroll
                        for (int nt2 = 0; nt2 < 8; nt2++) {
                            uint32_t bf[2];
                            bf[0] = Vs[(kb + ks * 8 + tg)     * 72 + nt2 * 8 + g];
                            bf[1] = Vs[(kb + ks * 8 + tg + 4) * 72 + nt2 * 8 + g];
                            mma_tf32(o[nt2], pa, bf);
                        }
                    }
                }
                __syncwarp();   // all warp lanes done reading Ps before next sub-tile overwrites
            }
        }
    }

    // ---- normalize + write head-interleaved [B,S,DA] ----
    float ilo = 1.0f / llo, ihi = 1.0f / lhi;
    int b = bh >> 4, h = bh & 15;
#pragma unroll
    for (int nt2 = 0; nt2 < 8; nt2++) {
        int d = nt2 * 8 + 2 * tg;
        float2 v0, v1;
        v0.x = o[nt2][0] * ilo; v0.y = o[nt2][1] * ilo;
        v1.x = o[nt2][2] * ihi; v1.y = o[nt2][3] * ihi;
        *(float2*)&g_att[((size_t)(b * SS + qlo)) * DMM + h * 64 + d] = v0;
        *(float2*)&g_att[((size_t)(b * SS + qhi)) * DMM + h * 64 + d] = v1;
    }
}

// ---------------- output projection, TF32 tensor-core GEMM ----------------
__global__ __launch_bounds__(256, 2) void k_out(
    const float* __restrict__ Wo, const float* __restrict__ bo, float* __restrict__ out)
{
    __shared__ uint32_t As[2][128 * AS_STRIDE];
    __shared__ uint32_t Bs[2][16 * BS_STRIDE];

    int bn = blockIdx.x * 128, bm = blockIdx.y * 128;

    int tid = threadIdx.x;
    int lane = tid & 31, wid = tid >> 5;
    int warpM = wid >> 2, warpN = wid & 3;
    int g = lane >> 2, tg = lane & 3;
    int arow = tid >> 2, ac = (tid & 3) * 4;
    int brow = tid >> 5, bc = (tid & 31) * 4;

    const float* Ap = g_att + (size_t)(bm + arow) * DMM + ac;
    const float* Bp = Wo + (size_t)brow * DMM + bn + bc;

    {
        float4 a0 = *(const float4*)Ap;
        float4 a1 = *(const float4*)(Ap + (size_t)64 * DMM);
        float4 b0 = *(const float4*)Bp;
        float4 b1 = *(const float4*)(Bp + (size_t)8 * DMM);
        uint32_t* p;
        p = &As[0][arow * AS_STRIDE + ac];
        p[0] = f2tf(a0.x); p[1] = f2tf(a0.y); p[2] = f2tf(a0.z); p[3] = f2tf(a0.w);
        p = &As[0][(arow + 64) * AS_STRIDE + ac];
        p[0] = f2tf(a1.x); p[1] = f2tf(a1.y); p[2] = f2tf(a1.z); p[3] = f2tf(a1.w);
        p = &Bs[0][brow * BS_STRIDE + bc];
        p[0] = f2tf(b0.x); p[1] = f2tf(b0.y); p[2] = f2tf(b0.z); p[3] = f2tf(b0.w);
        p = &Bs[0][(brow + 8) * BS_STRIDE + bc];
        p[0] = f2tf(b1.x); p[1] = f2tf(b1.y); p[2] = f2tf(b1.z); p[3] = f2tf(b1.w);
    }
    __syncthreads();

    float c[4][4][4];
#pragma unroll
    for (int mt = 0; mt < 4; mt++)
#pragma unroll
        for (int nt = 0; nt < 4; nt++)
#pragma unroll
            for (int r = 0; r < 4; r++) c[mt][nt][r] = 0.f;

    for (int it = 0; it < 64; it++) {
        int cur = it & 1;
        float4 a0, a1, b0, b1;
        bool more = (it < 63);
        if (more) {
            const float* Ap2 = Ap + (it + 1) * 16;
            const float* Bp2 = Bp + (size_t)(it + 1) * 16 * DMM;
            a0 = *(const float4*)Ap2;
            a1 = *(const float4*)(Ap2 + (size_t)64 * DMM);
            b0 = *(const float4*)Bp2;
            b1 = *(const float4*)(Bp2 + (size_t)8 * DMM);
        }
#pragma unroll
        for (int ks2 = 0; ks2 < 2; ks2++) {
            int ks = ks2 * 8;
            uint32_t af[4][4], bf[4][2];
#pragma unroll
            for (int mt = 0; mt < 4; mt++) {
                int rb = warpM * 64 + mt * 16;
                af[mt][0] = As[cur][(rb + g)     * AS_STRIDE + ks + tg];
                af[mt][1] = As[cur][(rb + g + 8) * AS_STRIDE + ks + tg];
                af[mt][2] = As[cur][(rb + g)     * AS_STRIDE + ks + tg + 4];
                af[mt][3] = As[cur][(rb + g + 8) * AS_STRIDE + ks + tg + 4];
            }
#pragma unroll
            for (int nt = 0; nt < 4; nt++) {
                int cb = warpN * 32 + nt * 8;
                bf[nt][0] = Bs[cur][(ks + tg)     * BS_STRIDE + cb + g];
                bf[nt][1] = Bs[cur][(ks + tg + 4) * BS_STRIDE + cb + g];
            }
#pragma unroll
            for (int mt = 0; mt < 4; mt++)
#pragma unroll
                for (int nt = 0; nt < 4; nt++)
                    mma_tf32(c[mt][nt], af[mt], bf[nt]);
        }
        if (more) {
            int nxt = cur ^ 1;
            uint32_t* p;
            p = &As[nxt][arow * AS_STRIDE + ac];
            p[0] = f2tf(a0.x); p[1] = f2tf(a0.y); p[2] = f2tf(a0.z); p[3] = f2tf(a0.w);
            p = &As[nxt][(arow + 64) * AS_STRIDE + ac];
            p[0] = f2tf(a1.x); p[1] = f2tf(a1.y); p[2] = f2tf(a1.z); p[3] = f2tf(a1.w);
            p = &Bs[nxt][brow * BS_STRIDE + bc];
            p[0] = f2tf(b0.x); p[1] = f2tf(b0.y); p[2] = f2tf(b0.z); p[3] = f2tf(b0.w);
            p = &Bs[nxt][(brow + 8) * BS_STRIDE + bc];
            p[0] = f2tf(b1.x); p[1] = f2tf(b1.y); p[2] = f2tf(b1.z); p[3] = f2tf(b1.w);
            __syncthreads();
        }
    }

#pragma unroll
    for (int mt = 0; mt < 4; mt++) {
#pragma unroll
        for (int nt = 0; nt < 4; nt++) {
            int n = bn + warpN * 32 + nt * 8 + 2 * tg;
            float b0v = bo[n], b1v = bo[n + 1];
            int m0 = bm + warpM * 64 + mt * 16 + g;
            float2 o0; o0.x = c[mt][nt][0] + b0v; o0.y = c[mt][nt][1] + b1v;
            float2 o1; o1.x = c[mt][nt][2] + b0v; o1.y = c[mt][nt][3] + b1v;
            *(float2*)&out[(size_t)m0 * DMM + n]       = o0;
            *(float2*)&out[(size_t)(m0 + 8) * DMM + n] = o1;
        }
    }
}

// ---------------- launch ----------------
extern "C" void kernel_launch(void* const* d_in, const int* in_sizes, int n_in,
                              void* d_out, int out_size)
{
    const float* x  = (const float*)d_in[0];
    const float* Wq = (const float*)d_in[1];
    const float* bq = (const float*)d_in[2];
    const float* Wk = (const float*)d_in[3];
    const float* bk = (const float*)d_in[4];
    const float* Wv = (const float*)d_in[5];
    const float* bv = (const float*)d_in[6];
    const float* Wo = (const float*)d_in[7];
    const float* bo = (const float*)d_in[8];
    const float* Er = (const float*)d_in[9];
    float* out = (float*)d_out;

    cudaFuncSetAttribute((const void*)k_attn,
                         cudaFuncAttributeMaxDynamicSharedMemorySize,
                         ATTN_SMEM_U32 * (int)sizeof(uint32_t));

    k_transpose_er<<<512, 256>>>(Er);
    k_qkv<<<dim3(24, 32), 256>>>(x, Wq, Wk, Wv, bq, bk, bv);
    k_rel<<<dim3(16, 16, 32), 256>>>();
    k_attn<<<dim3(16, 32), 256, ATTN_SMEM_U32 * sizeof(uint32_t)>>>();
    k_out<<<dim3(8, 32), 256>>>(Wo, bo, out);
}

// round 12
// speedup vs baseline: 1.1392x; 1.1392x over previous
#include <cuda_runtime.h>
#include <cuda_fp16.h>
#include <cstdint>

#define BB  2
#define SS  2048
#define DMM 1024
#define HH  16
#define DHH 64
#define BH  (BB*HH)   // 32

// ---------------- scratch (device globals; no runtime allocation) ----------------
__device__ float g_q[BB*HH*SS*DHH];
__device__ float g_k[BB*HH*SS*DHH];
__device__ float g_v[BB*HH*SS*DHH];
__device__ float g_att[BB*SS*DMM];
__device__ float g_erT[DHH*SS];          // Er[0:2048] transposed: [64][2048]
__device__ __half g_rel[134217728];      // PRE-SKEWED fp16: [BH][q][k] = Q[q]·Er[k+2047-q]

// ---------------- helpers ----------------
__device__ __forceinline__ uint32_t f2tf(float f) {
    uint32_t u;
    asm("cvt.rna.tf32.f32 %0, %1;" : "=r"(u) : "f"(f));
    return u;
}

__device__ __forceinline__ void mma_tf32(float* c, const uint32_t* a, const uint32_t* b) {
    asm("mma.sync.aligned.m16n8k8.row.col.f32.tf32.tf32.f32 "
        "{%0,%1,%2,%3},{%4,%5,%6,%7},{%8,%9},{%0,%1,%2,%3};"
        : "+f"(c[0]), "+f"(c[1]), "+f"(c[2]), "+f"(c[3])
        : "r"(a[0]), "r"(a[1]), "r"(a[2]), "r"(a[3]), "r"(b[0]), "r"(b[1]));
}

__device__ __forceinline__ void l2_prefetch(const void* p) {
    asm volatile("prefetch.global.L2 [%0];" :: "l"(p));
}

// ---------------- Er transpose ----------------
__global__ void k_transpose_er(const float* __restrict__ Er) {
    int idx = blockIdx.x * 256 + threadIdx.x;   // 0 .. 64*2048-1
    int r = idx & 2047;
    int d = idx >> 11;
    g_erT[idx] = Er[r * 64 + d];
}

// ---------------- fused QKV projection, TF32 tensor-core GEMM ----------------
#define AS_STRIDE 20
#define BS_STRIDE 136
__global__ __launch_bounds__(256, 2) void k_qkv(
    const float* __restrict__ x,
    const float* __restrict__ Wq, const float* __restrict__ Wk, const float* __restrict__ Wv,
    const float* __restrict__ bq, const float* __restrict__ bk, const float* __restrict__ bv)
{
    __shared__ uint32_t As[2][128 * AS_STRIDE];
    __shared__ uint32_t Bs[2][16 * BS_STRIDE];

    int bx = blockIdx.x, by = blockIdx.y;
    int which = bx >> 3;
    const float* W    = (which == 0) ? Wq : ((which == 1) ? Wk : Wv);
    const float* bias = (which == 0) ? bq : ((which == 1) ? bk : bv);
    float*       dst  = (which == 0) ? g_q : ((which == 1) ? g_k : g_v);
    int nb = (bx & 7) * 128;
    int bm = by * 128;

    int tid = threadIdx.x;
    int lane = tid & 31, wid = tid >> 5;
    int warpM = wid >> 2, warpN = wid & 3;
    int g = lane >> 2, tg = lane & 3;
    int arow = tid >> 2, ac = (tid & 3) * 4;
    int brow = tid >> 5, bc = (tid & 31) * 4;

    const float* Ap = x + (size_t)(bm + arow) * DMM + ac;
    const float* Bp = W + (size_t)brow * DMM + nb + bc;

    {
        float4 a0 = *(const float4*)Ap;
        float4 a1 = *(const float4*)(Ap + (size_t)64 * DMM);
        float4 b0 = *(const float4*)Bp;
        float4 b1 = *(const float4*)(Bp + (size_t)8 * DMM);
        uint32_t* p;
        p = &As[0][arow * AS_STRIDE + ac];
        p[0] = f2tf(a0.x); p[1] = f2tf(a0.y); p[2] = f2tf(a0.z); p[3] = f2tf(a0.w);
        p = &As[0][(arow + 64) * AS_STRIDE + ac];
        p[0] = f2tf(a1.x); p[1] = f2tf(a1.y); p[2] = f2tf(a1.z); p[3] = f2tf(a1.w);
        p = &Bs[0][brow * BS_STRIDE + bc];
        p[0] = f2tf(b0.x); p[1] = f2tf(b0.y); p[2] = f2tf(b0.z); p[3] = f2tf(b0.w);
        p = &Bs[0][(brow + 8) * BS_STRIDE + bc];
        p[0] = f2tf(b1.x); p[1] = f2tf(b1.y); p[2] = f2tf(b1.z); p[3] = f2tf(b1.w);
    }
    __syncthreads();

    float c[4][4][4];
#pragma unroll
    for (int mt = 0; mt < 4; mt++)
#pragma unroll
        for (int nt = 0; nt < 4; nt++)
#pragma unroll
            for (int r = 0; r < 4; r++) c[mt][nt][r] = 0.f;

    for (int it = 0; it < 64; it++) {
        int cur = it & 1;
        float4 a0, a1, b0, b1;
        bool more = (it < 63);
        if (more) {
            const float* Ap2 = Ap + (it + 1) * 16;
            const float* Bp2 = Bp + (size_t)(it + 1) * 16 * DMM;
            a0 = *(const float4*)Ap2;
            a1 = *(const float4*)(Ap2 + (size_t)64 * DMM);
            b0 = *(const float4*)Bp2;
            b1 = *(const float4*)(Bp2 + (size_t)8 * DMM);
        }
#pragma unroll
        for (int ks2 = 0; ks2 < 2; ks2++) {
            int ks = ks2 * 8;
            uint32_t af[4][4], bf[4][2];
#pragma unroll
            for (int mt = 0; mt < 4; mt++) {
                int rb = warpM * 64 + mt * 16;
                af[mt][0] = As[cur][(rb + g)     * AS_STRIDE + ks + tg];
                af[mt][1] = As[cur][(rb + g + 8) * AS_STRIDE + ks + tg];
                af[mt][2] = As[cur][(rb + g)     * AS_STRIDE + ks + tg + 4];
                af[mt][3] = As[cur][(rb + g + 8) * AS_STRIDE + ks + tg + 4];
            }
#pragma unroll
            for (int nt = 0; nt < 4; nt++) {
                int cb = warpN * 32 + nt * 8;
                bf[nt][0] = Bs[cur][(ks + tg)     * BS_STRIDE + cb + g];
                bf[nt][1] = Bs[cur][(ks + tg + 4) * BS_STRIDE + cb + g];
            }
#pragma unroll
            for (int mt = 0; mt < 4; mt++)
#pragma unroll
                for (int nt = 0; nt < 4; nt++)
                    mma_tf32(c[mt][nt], af[mt], bf[nt]);
        }
        if (more) {
            int nxt = cur ^ 1;
            uint32_t* p;
            p = &As[nxt][arow * AS_STRIDE + ac];
            p[0] = f2tf(a0.x); p[1] = f2tf(a0.y); p[2] = f2tf(a0.z); p[3] = f2tf(a0.w);
            p = &As[nxt][(arow + 64) * AS_STRIDE + ac];
            p[0] = f2tf(a1.x); p[1] = f2tf(a1.y); p[2] = f2tf(a1.z); p[3] = f2tf(a1.w);
            p = &Bs[nxt][brow * BS_STRIDE + bc];
            p[0] = f2tf(b0.x); p[1] = f2tf(b0.y); p[2] = f2tf(b0.z); p[3] = f2tf(b0.w);
            p = &Bs[nxt][(brow + 8) * BS_STRIDE + bc];
            p[0] = f2tf(b1.x); p[1] = f2tf(b1.y); p[2] = f2tf(b1.z); p[3] = f2tf(b1.w);
            __syncthreads();
        }
    }

#pragma unroll
    for (int mt = 0; mt < 4; mt++) {
#pragma unroll
        for (int nt = 0; nt < 4; nt++) {
            int nloc = nb + warpN * 32 + nt * 8 + 2 * tg;
            int h = nloc >> 6, d = nloc & 63;
            float b0v = bias[nloc], b1v = bias[nloc + 1];
            int m0 = bm + warpM * 64 + mt * 16 + g;
            int m1 = m0 + 8;
            {
                int b = m0 >> 11, s = m0 & 2047;
                float2 o; o.x = c[mt][nt][0] + b0v; o.y = c[mt][nt][1] + b1v;
                *(float2*)&dst[(((size_t)b * HH + h) * SS + s) * DHH + d] = o;
            }
            {
                int b = m1 >> 11, s = m1 & 2047;
                float2 o; o.x = c[mt][nt][2] + b0v; o.y = c[mt][nt][3] + b1v;
                *(float2*)&dst[(((size_t)b * HH + h) * SS + s) * DHH + d] = o;
            }
        }
    }
}

// ---------------- REL GEMM (TF32), skewed fp16 store: g_rel[q][k] = Q[q]·Er[k+2047-q] ----------------
__global__ __launch_bounds__(256, 2) void k_rel()
{
    int bh = blockIdx.z;
    int r0 = blockIdx.x * 128, q0 = blockIdx.y * 128;
    if (q0 + r0 < 1793) return;

    __shared__ uint32_t As[2][128 * AS_STRIDE];
    __shared__ uint32_t Bs[2][16 * BS_STRIDE];

    const float* A = g_q + (size_t)bh * SS * DHH;

    int tid = threadIdx.x;
    int lane = tid & 31, wid = tid >> 5;
    int warpM = wid >> 2, warpN = wid & 3;
    int g = lane >> 2, tg = lane & 3;
    int arow = tid >> 2, ac = (tid & 3) * 4;
    int brow = tid >> 5, bc = (tid & 31) * 4;

    const float* Ap = A + (size_t)(q0 + arow) * DHH + ac;
    const float* Bp = g_erT + (size_t)brow * SS + r0 + bc;

    {
        float4 a0 = *(const float4*)Ap;
        float4 a1 = *(const float4*)(Ap + (size_t)64 * DHH);
        float4 b0 = *(const float4*)Bp;
        float4 b1 = *(const float4*)(Bp + (size_t)8 * SS);
        uint32_t* p;
        p = &As[0][arow * AS_STRIDE + ac];
        p[0] = f2tf(a0.x); p[1] = f2tf(a0.y); p[2] = f2tf(a0.z); p[3] = f2tf(a0.w);
        p = &As[0][(arow + 64) * AS_STRIDE + ac];
        p[0] = f2tf(a1.x); p[1] = f2tf(a1.y); p[2] = f2tf(a1.z); p[3] = f2tf(a1.w);
        p = &Bs[0][brow * BS_STRIDE + bc];
        p[0] = f2tf(b0.x); p[1] = f2tf(b0.y); p[2] = f2tf(b0.z); p[3] = f2tf(b0.w);
        p = &Bs[0][(brow + 8) * BS_STRIDE + bc];
        p[0] = f2tf(b1.x); p[1] = f2tf(b1.y); p[2] = f2tf(b1.z); p[3] = f2tf(b1.w);
    }
    __syncthreads();

    float c[4][4][4];
#pragma unroll
    for (int mt = 0; mt < 4; mt++)
#pragma unroll
        for (int nt = 0; nt < 4; nt++)
#pragma unroll
            for (int r = 0; r < 4; r++) c[mt][nt][r] = 0.f;

    for (int it = 0; it < 4; it++) {
        int cur = it & 1;
        float4 a0, a1, b0, b1;
        bool more = (it < 3);
        if (more) {
            const float* Ap2 = Ap + (it + 1) * 16;
            const float* Bp2 = Bp + (size_t)(it + 1) * 16 * SS;
            a0 = *(const float4*)Ap2;
            a1 = *(const float4*)(Ap2 + (size_t)64 * DHH);
            b0 = *(const float4*)Bp2;
            b1 = *(const float4*)(Bp2 + (size_t)8 * SS);
        }
#pragma unroll
        for (int ks2 = 0; ks2 < 2; ks2++) {
            int ks = ks2 * 8;
            uint32_t af[4][4], bf[4][2];
#pragma unroll
            for (int mt = 0; mt < 4; mt++) {
                int rb = warpM * 64 + mt * 16;
                af[mt][0] = As[cur][(rb + g)     * AS_STRIDE + ks + tg];
                af[mt][1] = As[cur][(rb + g + 8) * AS_STRIDE + ks + tg];
                af[mt][2] = As[cur][(rb + g)     * AS_STRIDE + ks + tg + 4];
                af[mt][3] = As[cur][(rb + g + 8) * AS_STRIDE + ks + tg + 4];
            }
#pragma unroll
            for (int nt = 0; nt < 4; nt++) {
                int cb = warpN * 32 + nt * 8;
                bf[nt][0] = Bs[cur][(ks + tg)     * BS_STRIDE + cb + g];
                bf[nt][1] = Bs[cur][(ks + tg + 4) * BS_STRIDE + cb + g];
            }
#pragma unroll
            for (int mt = 0; mt < 4; mt++)
#pragma unroll
                for (int nt = 0; nt < 4; nt++)
                    mma_tf32(c[mt][nt], af[mt], bf[nt]);
        }
        if (more) {
            int nxt = cur ^ 1;
            uint32_t* p;
            p = &As[nxt][arow * AS_STRIDE + ac];
            p[0] = f2tf(a0.x); p[1] = f2tf(a0.y); p[2] = f2tf(a0.z); p[3] = f2tf(a0.w);
            p = &As[nxt][(arow + 64) * AS_STRIDE + ac];
            p[0] = f2tf(a1.x); p[1] = f2tf(a1.y); p[2] = f2tf(a1.z); p[3] = f2tf(a1.w);
            p = &Bs[nxt][brow * BS_STRIDE + bc];
            p[0] = f2tf(b0.x); p[1] = f2tf(b0.y); p[2] = f2tf(b0.z); p[3] = f2tf(b0.w);
            p = &Bs[nxt][(brow + 8) * BS_STRIDE + bc];
            p[0] = f2tf(b1.x); p[1] = f2tf(b1.y); p[2] = f2tf(b1.z); p[3] = f2tf(b1.w);
            __syncthreads();
        }
    }

    // skewed epilogue: element (m, col) -> g_rel[m][col - (2047 - m)] when in causal band
    __half* C = g_rel + (size_t)bh * SS * SS;
#pragma unroll
    for (int mt = 0; mt < 4; mt++) {
#pragma unroll
        for (int nt = 0; nt < 4; nt++) {
            int col = r0 + warpN * 32 + nt * 8 + 2 * tg;
            int m0 = q0 + warpM * 64 + mt * 16 + g;
            int m1 = m0 + 8;
            int k0e = col - 2047 + m0;
            int k1e = col - 2047 + m1;
            if (k0e >= 0)     C[(size_t)m0 * SS + k0e]     = __float2half(c[mt][nt][0]);
            if (k0e + 1 >= 0) C[(size_t)m0 * SS + k0e + 1] = __float2half(c[mt][nt][1]);
            if (k1e >= 0)     C[(size_t)m1 * SS + k1e]     = __float2half(c[mt][nt][2]);
            if (k1e + 1 >= 0) C[(size_t)m1 * SS + k1e + 1] = __float2half(c[mt][nt][3]);
        }
    }
}

// ---------------- flash attention, TF32 tensor cores, 256 threads, 2 CTAs/SM ----------------
// 8 warps x 16 q-rows = 128 q per block; Bk = 64, single-buffered K/V, cross-CTA overlap.
// L2 prefetch: rel-bias rows at tile start; next tile's K/V lines during compute.
// smem (u32): Ks[64*68] | Vs[64*72] | Ps[128*68] = 17664 u32 = 70656 B  (2 CTAs -> 141312 B/SM)
#define ATTN_SMEM_U32 (64*68 + 64*72 + 128*68)

__global__ __launch_bounds__(256, 2) void k_attn()
{
    extern __shared__ uint32_t smu[];
    uint32_t* Ks = smu;                 // [k][d] stride 68 (raw fp32 bits)
    uint32_t* Vs = Ks + 64 * 68;        // [k][d] stride 72 (raw fp32 bits)
    uint32_t* Ps = Vs + 64 * 72;        // [q][k] stride 68 (per-warp-private rows)

    int bh = blockIdx.y;
    int qt = (int)gridDim.x - 1 - (int)blockIdx.x;   // heavy tiles first
    int q0 = qt * 128;
    const float*  Q  = g_q + (size_t)bh * SS * DHH;
    const float*  Kp = g_k + (size_t)bh * SS * DHH;
    const float*  Vp = g_v + (size_t)bh * SS * DHH;
    const __half* R  = g_rel + (size_t)bh * SS * SS;

    int tid = threadIdx.x;
    int lane = tid & 31, wid = tid >> 5;   // wid 0..7
    int g = lane >> 2, tg = lane & 3;
    int qbase = q0 + wid * 16;
    int qlo = qbase + g, qhi = qlo + 8;

    // Q A-fragments in registers, loaded once, reused for every k-tile
    uint32_t qa[8][4];
#pragma unroll
    for (int ks = 0; ks < 8; ks++) {
        qa[ks][0] = f2tf(Q[(size_t)qlo * DHH + ks * 8 + tg]);
        qa[ks][1] = f2tf(Q[(size_t)qhi * DHH + ks * 8 + tg]);
        qa[ks][2] = f2tf(Q[(size_t)qlo * DHH + ks * 8 + tg + 4]);
        qa[ks][3] = f2tf(Q[(size_t)qhi * DHH + ks * 8 + tg + 4]);
    }

    float o[8][4];
#pragma unroll
    for (int nt = 0; nt < 8; nt++) { o[nt][0] = o[nt][1] = o[nt][2] = o[nt][3] = 0.f; }
    float mlo = -3.0e38f, mhi = -3.0e38f, llo = 0.f, lhi = 0.f;

    int prow_lo = (wid * 16 + g) * 68;
    int prow_hi = (wid * 16 + g + 8) * 68;

    int ntiles = 2 * qt + 2;   // k up to q0+127
    for (int t = 0; t < ntiles; t++) {
        int k0 = t * 64;
        // prefetch this tile's rel-bias rows into L2 (one 128B line covers all 64 keys)
        if (k0 <= qbase + 15) {
            l2_prefetch(&R[(size_t)qlo * SS + k0]);
            l2_prefetch(&R[(size_t)qhi * SS + k0]);
        }
        __syncthreads();   // prior tile's reads of Ks/Vs done
        // stage K/V raw fp32 bits (TF32-truncated by the MMA), 4 x uint4 per thread
#pragma unroll
        for (int i = 0; i < 4; i++) {
            int idx = i * 256 + tid;               // 0..1023
            int ki = idx >> 4, c4 = (idx & 15) * 4;
            uint4 kv = *(const uint4*)&Kp[(size_t)(k0 + ki) * DHH + c4];
            *(uint4*)&Ks[ki * 68 + c4] = kv;
            uint4 vv = *(const uint4*)&Vp[(size_t)(k0 + ki) * DHH + c4];
            *(uint4*)&Vs[ki * 72 + c4] = vv;
        }
        __syncthreads();

        // prefetch next tile's K/V lines into L2 (128 lines each; 256 threads cover both)
        if (t + 1 < ntiles) {
            int kn = (t + 1) * 64;
            if (tid < 128) l2_prefetch(&Kp[(size_t)(kn + (tid >> 1)) * DHH + (tid & 1) * 32]);
            else { int u = tid - 128; l2_prefetch(&Vp[(size_t)(kn + (u >> 1)) * DHH + (u & 1) * 32]); }
        }

        // warp-uniform causal bound (can be <= 0 for low warps at late tiles)
        int ntmax = min(8, ((qbase + 15 - k0) >> 3) + 1);
        if (ntmax > 0) {
            // ---- scores S = Q·K^T ----
            float s[8][4];
#pragma unroll
            for (int nt = 0; nt < 8; nt++) { s[nt][0] = s[nt][1] = s[nt][2] = s[nt][3] = 0.f; }
#pragma unroll
            for (int ks = 0; ks < 8; ks++) {
#pragma unroll
                for (int nt = 0; nt < 8; nt++) {
                    if (nt < ntmax) {
                        uint32_t bf[2];
                        bf[0] = Ks[(nt * 8 + g) * 68 + ks * 8 + tg];
                        bf[1] = Ks[(nt * 8 + g) * 68 + ks * 8 + tg + 4];
                        mma_tf32(s[nt], qa[ks], bf);
                    }
                }
            }

            // ---- + rel bias (fp16, aligned half2), scale, causal mask ----
            float tmlo = -3.0e38f, tmhi = -3.0e38f;
#pragma unroll
            for (int nt = 0; nt < 8; nt++) {
                if (nt < ntmax) {
                    int kk = k0 + nt * 8 + 2 * tg;
                    float2 rlo = __half22float2(*(const __half2*)&R[(size_t)qlo * SS + kk]);
                    float2 rhi = __half22float2(*(const __half2*)&R[(size_t)qhi * SS + kk]);
                    s[nt][0] = (kk     <= qlo) ? (s[nt][0] + rlo.x) * 0.125f : -1.0e30f;
                    s[nt][1] = (kk + 1 <= qlo) ? (s[nt][1] + rlo.y) * 0.125f : -1.0e30f;
                    s[nt][2] = (kk     <= qhi) ? (s[nt][2] + rhi.x) * 0.125f : -1.0e30f;
                    s[nt][3] = (kk + 1 <= qhi) ? (s[nt][3] + rhi.y) * 0.125f : -1.0e30f;
                    tmlo = fmaxf(tmlo, fmaxf(s[nt][0], s[nt][1]));
                    tmhi = fmaxf(tmhi, fmaxf(s[nt][2], s[nt][3]));
                }
            }

            // ---- online softmax (rows live in 4 tg lanes -> 2 shfls) ----
            tmlo = fmaxf(tmlo, __shfl_xor_sync(0xffffffffu, tmlo, 1));
            tmlo = fmaxf(tmlo, __shfl_xor_sync(0xffffffffu, tmlo, 2));
            tmhi = fmaxf(tmhi, __shfl_xor_sync(0xffffffffu, tmhi, 1));
            tmhi = fmaxf(tmhi, __shfl_xor_sync(0xffffffffu, tmhi, 2));
            float mnlo = fmaxf(mlo, tmlo), mnhi = fmaxf(mhi, tmhi);
            float clo = __expf(mlo - mnlo), chi = __expf(mhi - mnhi);
            mlo = mnlo; mhi = mnhi;

            float rslo = 0.f, rshi = 0.f;
#pragma unroll
            for (int nt = 0; nt < 8; nt++) {
                if (nt < ntmax) {
                    float p0 = __expf(s[nt][0] - mnlo);
                    float p1 = __expf(s[nt][1] - mnlo);
                    float p2 = __expf(s[nt][2] - mnhi);
                    float p3 = __expf(s[nt][3] - mnhi);
                    rslo += p0 + p1;
                    rshi += p2 + p3;
                    int col = nt * 8 + 2 * tg;
                    *(uint2*)&Ps[prow_lo + col] = make_uint2(f2tf(p0), f2tf(p1));
                    *(uint2*)&Ps[prow_hi + col] = make_uint2(f2tf(p2), f2tf(p3));
                }
            }
            rslo += __shfl_xor_sync(0xffffffffu, rslo, 1);
            rslo += __shfl_xor_sync(0xffffffffu, rslo, 2);
            rshi += __shfl_xor_sync(0xffffffffu, rshi, 1);
            rshi += __shfl_xor_sync(0xffffffffu, rshi, 2);
            llo = llo * clo + rslo;
            lhi = lhi * chi + rshi;
#pragma unroll
            for (int nt2 = 0; nt2 < 8; nt2++) {
                o[nt2][0] *= clo; o[nt2][1] *= clo;
                o[nt2][2] *= chi; o[nt2][3] *= chi;
            }

            __syncwarp();   // Ps rows are warp-private: warp-level ordering suffices

            // ---- O += P·V (skip k-groups where P == 0) ----
#pragma unroll
            for (int ks = 0; ks < 8; ks++) {
                if (ks < ntmax) {
                    uint32_t pa[4];
                    pa[0] = Ps[prow_lo + ks * 8 + tg];
                    pa[1] = Ps[prow_hi + ks * 8 + tg];
                    pa[2] = Ps[prow_lo + ks * 8 + tg + 4];
                    pa[3] = Ps[prow_hi + ks * 8 + tg + 4];
#pragma unroll
                    for (int nt2 = 0; nt2 < 8; nt2++) {
                        uint32_t bf[2];
                        bf[0] = Vs[(ks * 8 + tg)     * 72 + nt2 * 8 + g];
                        bf[1] = Vs[(ks * 8 + tg + 4) * 72 + nt2 * 8 + g];
                        mma_tf32(o[nt2], pa, bf);
                    }
                }
            }
        }
    }

    // ---- normalize + write head-interleaved [B,S,DA] ----
    float ilo = 1.0f / llo, ihi = 1.0f / lhi;
    int b = bh >> 4, h = bh & 15;
#pragma unroll
    for (int nt2 = 0; nt2 < 8; nt2++) {
        int d = nt2 * 8 + 2 * tg;
        float2 v0, v1;
        v0.x = o[nt2][0] * ilo; v0.y = o[nt2][1] * ilo;
        v1.x = o[nt2][2] * ihi; v1.y = o[nt2][3] * ihi;
        *(float2*)&g_att[((size_t)(b * SS + qlo)) * DMM + h * 64 + d] = v0;
        *(float2*)&g_att[((size_t)(b * SS + qhi)) * DMM + h * 64 + d] = v1;
    }
}

// ---------------- output projection, TF32 tensor-core GEMM ----------------
__global__ __launch_bounds__(256, 2) void k_out(
    const float* __restrict__ Wo, const float* __restrict__ bo, float* __restrict__ out)
{
    __shared__ uint32_t As[2][128 * AS_STRIDE];
    __shared__ uint32_t Bs[2][16 * BS_STRIDE];

    int bn = blockIdx.x * 128, bm = blockIdx.y * 128;

    int tid = threadIdx.x;
    int lane = tid & 31, wid = tid >> 5;
    int warpM = wid >> 2, warpN = wid & 3;
    int g = lane >> 2, tg = lane & 3;
    int arow = tid >> 2, ac = (tid & 3) * 4;
    int brow = tid >> 5, bc = (tid & 31) * 4;

    const float* Ap = g_att + (size_t)(bm + arow) * DMM + ac;
    const float* Bp = Wo + (size_t)brow * DMM + bn + bc;

    {
        float4 a0 = *(const float4*)Ap;
        float4 a1 = *(const float4*)(Ap + (size_t)64 * DMM);
        float4 b0 = *(const float4*)Bp;
        float4 b1 = *(const float4*)(Bp + (size_t)8 * DMM);
        uint32_t* p;
        p = &As[0][arow * AS_STRIDE + ac];
        p[0] = f2tf(a0.x); p[1] = f2tf(a0.y); p[2] = f2tf(a0.z); p[3] = f2tf(a0.w);
        p = &As[0][(arow + 64) * AS_STRIDE + ac];
        p[0] = f2tf(a1.x); p[1] = f2tf(a1.y); p[2] = f2tf(a1.z); p[3] = f2tf(a1.w);
        p = &Bs[0][brow * BS_STRIDE + bc];
        p[0] = f2tf(b0.x); p[1] = f2tf(b0.y); p[2] = f2tf(b0.z); p[3] = f2tf(b0.w);
        p = &Bs[0][(brow + 8) * BS_STRIDE + bc];
        p[0] = f2tf(b1.x); p[1] = f2tf(b1.y); p[2] = f2tf(b1.z); p[3] = f2tf(b1.w);
    }
    __syncthreads();

    float c[4][4][4];
#pragma unroll
    for (int mt = 0; mt < 4; mt++)
#pragma unroll
        for (int nt = 0; nt < 4; nt++)
#pragma unroll
            for (int r = 0; r < 4; r++) c[mt][nt][r] = 0.f;

    for (int it = 0; it < 64; it++) {
        int cur = it & 1;
        float4 a0, a1, b0, b1;
        bool more = (it < 63);
        if (more) {
            const float* Ap2 = Ap + (it + 1) * 16;
            const float* Bp2 = Bp + (size_t)(it + 1) * 16 * DMM;
            a0 = *(const float4*)Ap2;
            a1 = *(const float4*)(Ap2 + (size_t)64 * DMM);
            b0 = *(const float4*)Bp2;
            b1 = *(const float4*)(Bp2 + (size_t)8 * DMM);
        }
#pragma unroll
        for (int ks2 = 0; ks2 < 2; ks2++) {
            int ks = ks2 * 8;
            uint32_t af[4][4], bf[4][2];
#pragma unroll
            for (int mt = 0; mt < 4; mt++) {
                int rb = warpM * 64 + mt * 16;
                af[mt][0] = As[cur][(rb + g)     * AS_STRIDE + ks + tg];
                af[mt][1] = As[cur][(rb + g + 8) * AS_STRIDE + ks + tg];
                af[mt][2] = As[cur][(rb + g)     * AS_STRIDE + ks + tg + 4];
                af[mt][3] = As[cur][(rb + g + 8) * AS_STRIDE + ks + tg + 4];
            }
#pragma unroll
            for (int nt = 0; nt < 4; nt++) {
                int cb = warpN * 32 + nt * 8;
                bf[nt][0] = Bs[cur][(ks + tg)     * BS_STRIDE + cb + g];
                bf[nt][1] = Bs[cur][(ks + tg + 4) * BS_STRIDE + cb + g];
            }
#pragma unroll
            for (int mt = 0; mt < 4; mt++)
#pragma unroll
                for (int nt = 0; nt < 4; nt++)
                    mma_tf32(c[mt][nt], af[mt], bf[nt]);
        }
        if (more) {
            int nxt = cur ^ 1;
            uint32_t* p;
            p = &As[nxt][arow * AS_STRIDE + ac];
            p[0] = f2tf(a0.x); p[1] = f2tf(a0.y); p[2] = f2tf(a0.z); p[3] = f2tf(a0.w);
            p = &As[nxt][(arow + 64) * AS_STRIDE + ac];
            p[0] = f2tf(a1.x); p[1] = f2tf(a1.y); p[2] = f2tf(a1.z); p[3] = f2tf(a1.w);
            p = &Bs[nxt][brow * BS_STRIDE + bc];
            p[0] = f2tf(b0.x); p[1] = f2tf(b0.y); p[2] = f2tf(b0.z); p[3] = f2tf(b0.w);
            p = &Bs[nxt][(brow + 8) * BS_STRIDE + bc];
            p[0] = f2tf(b1.x); p[1] = f2tf(b1.y); p[2] = f2tf(b1.z); p[3] = f2tf(b1.w);
            __syncthreads();
        }
    }

#pragma unroll
    for (int mt = 0; mt < 4; mt++) {
#pragma unroll
        for (int nt = 0; nt < 4; nt++) {
            int n = bn + warpN * 32 + nt * 8 + 2 * tg;
            float b0v = bo[n], b1v = bo[n + 1];
            int m0 = bm + warpM * 64 + mt * 16 + g;
            float2 o0; o0.x = c[mt][nt][0] + b0v; o0.y = c[mt][nt][1] + b1v;
            float2 o1; o1.x = c[mt][nt][2] + b0v; o1.y = c[mt][nt][3] + b1v;
            *(float2*)&out[(size_t)m0 * DMM + n]       = o0;
            *(float2*)&out[(size_t)(m0 + 8) * DMM + n] = o1;
        }
    }
}

// ---------------- launch ----------------
extern "C" void kernel_launch(void* const* d_in, const int* in_sizes, int n_in,
                              void* d_out, int out_size)
{
    const float* x  = (const float*)d_in[0];
    const float* Wq = (const float*)d_in[1];
    const float* bq = (const float*)d_in[2];
    const float* Wk = (const float*)d_in[3];
    const float* bk = (const float*)d_in[4];
    const float* Wv = (const float*)d_in[5];
    const float* bv = (const float*)d_in[6];
    const float* Wo = (const float*)d_in[7];
    const float* bo = (const float*)d_in[8];
    const float* Er = (const float*)d_in[9];
    float* out = (float*)d_out;

    cudaFuncSetAttribute((const void*)k_attn,
                         cudaFuncAttributeMaxDynamicSharedMemorySize,
                         ATTN_SMEM_U32 * (int)sizeof(uint32_t));

    k_transpose_er<<<512, 256>>>(Er);
    k_qkv<<<dim3(24, 32), 256>>>(x, Wq, Wk, Wv, bq, bk, bv);
    k_rel<<<dim3(16, 16, 32), 256>>>();
    k_attn<<<dim3(16, 32), 256, ATTN_SMEM_U32 * sizeof(uint32_t)>>>();
    k_out<<<dim3(8, 32), 256>>>(Wo, bo, out);
}